// round 15
// baseline (speedup 1.0000x reference)
#include <cuda_runtime.h>

// out[i, j] = filt[i] * x[i, j].  Nominal: x [8192, 4096] fp32, filt [8192] fp32.
// Flat launch, one CTA = one 1024-float4 tile (== one row at m=4096).
// 256 threads x 4 front-batched independent float4 loads (best-measured form),
// one broadcast filt scalar per block. Loads: evict-first (__ldcs).
// Stores: write-through (__stwt) — touch-once output, keep it out of L2 so the
// read stream owns the cache and DRAM write scheduling isn't writeback-driven.

__global__ __launch_bounds__(256) void diag_scale_row4(
    const float4* __restrict__ x,
    const float* __restrict__ filt,
    float4* __restrict__ out,
    int tiles_per_row_shift)     // log2(row_f4 / 1024)
{
    int tile = blockIdx.x;
    int row  = tile >> tiles_per_row_shift;
    float f  = __ldg(&filt[row]);            // L2-resident broadcast, one per block

    int base = (tile << 10) + threadIdx.x;   // tile * 1024 + tid

    // Front-batch all 4 independent loads (evict-first).
    float4 v0 = __ldcs(&x[base]);
    float4 v1 = __ldcs(&x[base + 256]);
    float4 v2 = __ldcs(&x[base + 512]);
    float4 v3 = __ldcs(&x[base + 768]);

    v0.x *= f; v0.y *= f; v0.z *= f; v0.w *= f;
    v1.x *= f; v1.y *= f; v1.z *= f; v1.w *= f;
    v2.x *= f; v2.y *= f; v2.z *= f; v2.w *= f;
    v3.x *= f; v3.y *= f; v3.z *= f; v3.w *= f;

    __stwt(&out[base],       v0);
    __stwt(&out[base + 256], v1);
    __stwt(&out[base + 512], v2);
    __stwt(&out[base + 768], v3);
}

// Fallback for shapes that don't tile to 1024 float4 per row chunk.
__global__ __launch_bounds__(256) void diag_scale_scalar_kernel(
    const float* __restrict__ x,
    const float* __restrict__ filt,
    float* __restrict__ out,
    int total, int m)
{
    int idx = blockIdx.x * blockDim.x + threadIdx.x;
    if (idx >= total) return;
    out[idx] = x[idx] * __ldg(&filt[idx / m]);
}

extern "C" void kernel_launch(void* const* d_in, const int* in_sizes, int n_in,
                              void* d_out, int out_size)
{
    const float* x    = (const float*)d_in[0];
    const float* filt = (const float*)d_in[1];
    float* out        = (float*)d_out;

    int total  = in_sizes[0];        // n * m
    int n_filt = in_sizes[1];        // n
    int m      = total / n_filt;     // 4096 nominally

    int row_f4 = m >> 2;             // float4 per row (1024 nominal)
    bool fast = (m % 4 == 0) && (row_f4 >= 1024) && ((row_f4 & (row_f4 - 1)) == 0);

    if (fast) {
        int tiles_per_row = row_f4 >> 10;           // power of two
        int shift = 0;
        while ((1 << shift) < tiles_per_row) shift++;
        int blocks = n_filt * tiles_per_row;        // 8192 nominal
        diag_scale_row4<<<blocks, 256>>>(
            (const float4*)x, filt, (float4*)out, shift);
    } else {
        int threads = 256;
        int blocks = (total + threads - 1) / threads;
        diag_scale_scalar_kernel<<<blocks, threads>>>(x, filt, out, total, m);
    }
}

// round 17
// speedup vs baseline: 1.0426x; 1.0426x over previous
#include <cuda_runtime.h>

// out[i, j] = filt[i] * x[i, j].  Nominal: x [8192, 4096] fp32, filt [8192] fp32.
// Best-measured form (rounds 8/9: 35.71us kernel, 5.98 TB/s = 75% HBM):
// flat launch, one CTA = one 1024-float4 tile (== one row at m=4096),
// 256 threads x 4 front-batched independent float4 loads (MLP=4),
// one broadcast filt scalar per block, evict-first load + store hints.
// Measured ceiling is HBM R/W-turnaround (~75% of 8 TB/s); MLP {2,4,8},
// occupancy 59-83%, persistent grid, and __stwt all failed to move it.

__global__ __launch_bounds__(256) void diag_scale_row4(
    const float4* __restrict__ x,
    const float* __restrict__ filt,
    float4* __restrict__ out,
    int tiles_per_row_shift)     // log2(row_f4 / 1024)
{
    int tile = blockIdx.x;
    int row  = tile >> tiles_per_row_shift;
    float f  = __ldg(&filt[row]);            // L2-resident broadcast, one per block

    int base = (tile << 10) + threadIdx.x;   // tile * 1024 + tid

    // Front-batch all 4 independent loads (evict-first).
    float4 v0 = __ldcs(&x[base]);
    float4 v1 = __ldcs(&x[base + 256]);
    float4 v2 = __ldcs(&x[base + 512]);
    float4 v3 = __ldcs(&x[base + 768]);

    v0.x *= f; v0.y *= f; v0.z *= f; v0.w *= f;
    v1.x *= f; v1.y *= f; v1.z *= f; v1.w *= f;
    v2.x *= f; v2.y *= f; v2.z *= f; v2.w *= f;
    v3.x *= f; v3.y *= f; v3.z *= f; v3.w *= f;

    __stcs(&out[base],       v0);
    __stcs(&out[base + 256], v1);
    __stcs(&out[base + 512], v2);
    __stcs(&out[base + 768], v3);
}

// Fallback for shapes that don't tile to 1024 float4 per row chunk.
__global__ __launch_bounds__(256) void diag_scale_scalar_kernel(
    const float* __restrict__ x,
    const float* __restrict__ filt,
    float* __restrict__ out,
    int total, int m)
{
    int idx = blockIdx.x * blockDim.x + threadIdx.x;
    if (idx >= total) return;
    out[idx] = x[idx] * __ldg(&filt[idx / m]);
}

extern "C" void kernel_launch(void* const* d_in, const int* in_sizes, int n_in,
                              void* d_out, int out_size)
{
    const float* x    = (const float*)d_in[0];
    const float* filt = (const float*)d_in[1];
    float* out        = (float*)d_out;

    int total  = in_sizes[0];        // n * m
    int n_filt = in_sizes[1];        // n
    int m      = total / n_filt;     // 4096 nominally

    int row_f4 = m >> 2;             // float4 per row (1024 nominal)
    bool fast = (m % 4 == 0) && (row_f4 >= 1024) && ((row_f4 & (row_f4 - 1)) == 0);

    if (fast) {
        int tiles_per_row = row_f4 >> 10;           // power of two
        int shift = 0;
        while ((1 << shift) < tiles_per_row) shift++;
        int blocks = n_filt * tiles_per_row;        // 8192 nominal
        diag_scale_row4<<<blocks, 256>>>(
            (const float4*)x, filt, (float4*)out, shift);
    } else {
        int threads = 256;
        int blocks = (total + threads - 1) / threads;
        diag_scale_scalar_kernel<<<blocks, threads>>>(x, filt, out, total, m);
    }
}